// round 1
// baseline (speedup 1.0000x reference)
#include <cuda_runtime.h>
#include <cuda_bf16.h>
#include <cstdint>

// ---------------------------------------------------------------------------
// Problem constants
// ---------------------------------------------------------------------------
#define NSAMP 65536
#define T_STEPS 28
#define V_IN 28
#define H_DIM 64
#define L_LAYERS 7
#define F_TOT (T_STEPS * V_IN)   // 784

// ---------------------------------------------------------------------------
// Scratch (static __device__ arrays: the sanctioned no-alloc workaround)
//   g_xT : transposed input  [t*28+i][sample]           (205 MB)
//   g_act: activations       [t*64+j][sample], in-place (470 MB)
// ---------------------------------------------------------------------------
__device__ float g_xT[(size_t)F_TOT * NSAMP];
__device__ float g_act[(size_t)T_STEPS * H_DIM * NSAMP];

// ---------------------------------------------------------------------------
// Helpers
// ---------------------------------------------------------------------------
__device__ __forceinline__ void fma2(unsigned long long& acc,
                                     unsigned long long w,
                                     unsigned long long v) {
    asm("fma.rn.f32x2 %0, %1, %2, %0;" : "+l"(acc) : "l"(w), "l"(v));
}

__device__ __forceinline__ unsigned long long pack2(float v) {
    unsigned long long r;
    asm("mov.b64 %0, {%1, %1};" : "=l"(r) : "f"(v));
    return r;
}

__device__ __forceinline__ void unpack2(unsigned long long p, float& a, float& b) {
    asm("mov.b64 {%0, %1}, %2;" : "=f"(a), "=f"(b) : "l"(p));
}

// Accurate-enough fast tanh: 1 - 2/(exp(2x)+1). ex2.approx ~2ulp -> ~1e-6 rel.
// Saturation-safe: exp->inf gives 1, exp->0 gives -1.
__device__ __forceinline__ float fast_tanh(float x) {
    float e = __expf(2.0f * x);
    return 1.0f - __fdividef(2.0f, e + 1.0f);
}

__device__ __forceinline__ void cp_async16(void* smem_dst, const void* gmem_src) {
    unsigned sm = (unsigned)__cvta_generic_to_shared(smem_dst);
    asm volatile("cp.async.cg.shared.global [%0], [%1], 16;" :: "r"(sm), "l"(gmem_src));
}
__device__ __forceinline__ void cp_commit() {
    asm volatile("cp.async.commit_group;");
}
__device__ __forceinline__ void cp_wait0() {
    asm volatile("cp.async.wait_group 0;" ::: "memory");
}

// ---------------------------------------------------------------------------
// Kernel 1: tiled transpose x (N,784) -> g_xT (784,N)
// ---------------------------------------------------------------------------
__global__ void transpose_kernel(const float* __restrict__ x) {
    __shared__ float tile[32][33];
    const int s0 = blockIdx.x * 32;
    const int f0 = blockIdx.y * 32;
    const int tx = threadIdx.x, ty = threadIdx.y;

#pragma unroll
    for (int r = 0; r < 32; r += 8) {
        int f = f0 + tx;
        float v = 0.f;
        if (f < F_TOT)
            v = x[(size_t)(s0 + ty + r) * F_TOT + f];
        tile[ty + r][tx] = v;
    }
    __syncthreads();
#pragma unroll
    for (int r = 0; r < 32; r += 8) {
        int f = f0 + ty + r;
        if (f < F_TOT)
            g_xT[(size_t)f * NSAMP + s0 + tx] = tile[tx][ty + r];
    }
}

// ---------------------------------------------------------------------------
// Kernel 2: one RNN layer, fused input-projection + recurrence.
//   One thread per sample; 128 samples per block.
//   Dynamic SMEM layout (floats):
//     sW  [0      .. 8192)   transposed weights: rows 0..IN-1 = Wih^T,
//                            rows IN..IN+63 = Whh^T  (row m: 64 floats [j])
//     sB  [8192   .. 8256)   combined bias bih+bhh
//     sIn [8256   .. 24640)  rows 0..IN-1: staged x_t slice [i][128 samples]
//                            rows IN..IN+63: hidden state   [k][128 samples]
// ---------------------------------------------------------------------------
#define SMEM_FLOATS (8192 + 64 + 16384)
#define SMEM_BYTES  (SMEM_FLOATS * 4)

__global__ __launch_bounds__(128) void rnn_layer_kernel(
    int layer, int IN,
    const float* __restrict__ Wih, const float* __restrict__ Whh,
    const float* __restrict__ bih, const float* __restrict__ bhh)
{
    extern __shared__ float smem[];
    float* sW  = smem;
    float* sB  = smem + 8192;
    float* sIn = smem + 8256;

    const int tid = threadIdx.x;
    const float* xin = (layer == 0) ? g_xT : g_act;

    // Load transposed weights: sW[m*64 + j]
    for (int idx = tid; idx < IN * 64; idx += 128) {
        int i = idx >> 6, j = idx & 63;
        sW[idx] = Wih[j * IN + i];
    }
    for (int idx = tid; idx < 64 * 64; idx += 128) {
        int k = idx >> 6, j = idx & 63;
        sW[IN * 64 + idx] = Whh[j * 64 + k];
    }
    if (tid < 64) sB[tid] = bih[tid] + bhh[tid];

    // h = 0 (each thread owns column `tid`)
#pragma unroll
    for (int k = 0; k < 64; k++) sIn[(IN + k) * 128 + tid] = 0.0f;
    __syncthreads();

    const int s0 = blockIdx.x * 128;
    const int s  = s0 + tid;
    unsigned long long p2[32];

    for (int t = 0; t < T_STEPS; t++) {
        // ---- stage x_t slice for this block's 128 samples (async) ----
        {
            const float* src = xin + (size_t)t * IN * NSAMP + s0;
            for (int v = tid; v < IN * 32; v += 128) {
                int i = v >> 5, c = v & 31;
                cp_async16(&sIn[i * 128 + 4 * c], src + (size_t)i * NSAMP + 4 * c);
            }
            cp_commit();
        }

        // ---- init accumulators with combined bias ----
#pragma unroll
        for (int jp = 0; jp < 32; jp++) {
            float2 b = *reinterpret_cast<const float2*>(&sB[2 * jp]);
            asm("mov.b64 %0, {%1, %2};" : "=l"(p2[jp]) : "f"(b.x), "f"(b.y));
        }

        // ---- recurrent half first (overlaps with cp.async of x_t) ----
        {
            const float* hcol = sIn + IN * 128 + tid;
            const float* wrow = sW + IN * 64;
#pragma unroll 2
            for (int k = 0; k < 64; k++) {
                float v = hcol[k * 128];
                unsigned long long vv = pack2(v);
                const ulonglong2* w = reinterpret_cast<const ulonglong2*>(wrow + k * 64);
#pragma unroll
                for (int q = 0; q < 16; q++) {
                    ulonglong2 ww = w[q];
                    fma2(p2[2 * q],     ww.x, vv);
                    fma2(p2[2 * q + 1], ww.y, vv);
                }
            }
        }

        cp_wait0();
        __syncthreads();

        // ---- input-projection half ----
        {
#pragma unroll 2
            for (int i = 0; i < IN; i++) {
                float v = sIn[i * 128 + tid];
                unsigned long long vv = pack2(v);
                const ulonglong2* w = reinterpret_cast<const ulonglong2*>(sW + i * 64);
#pragma unroll
                for (int q = 0; q < 16; q++) {
                    ulonglong2 ww = w[q];
                    fma2(p2[2 * q],     ww.x, vv);
                    fma2(p2[2 * q + 1], ww.y, vv);
                }
            }
        }

        // ---- tanh, write h back to SMEM (own column) and to gmem ----
        {
            float* gout = g_act + (size_t)t * H_DIM * NSAMP + s;
#pragma unroll
            for (int jp = 0; jp < 32; jp++) {
                float a, b;
                unpack2(p2[jp], a, b);
                a = fast_tanh(a);
                b = fast_tanh(b);
                sIn[(IN + 2 * jp) * 128 + tid]     = a;
                sIn[(IN + 2 * jp + 1) * 128 + tid] = b;
                gout[(size_t)(2 * jp) * NSAMP]     = a;
                gout[(size_t)(2 * jp + 1) * NSAMP] = b;
            }
        }
        __syncthreads();  // protect x rows before next step's cp.async
    }
}

// ---------------------------------------------------------------------------
// Kernel 3: classifier head  out[s][c] = bc[c] + sum_j Wc[c][j] * h_last[j][s]
// ---------------------------------------------------------------------------
__global__ __launch_bounds__(128) void head_kernel(
    const float* __restrict__ Wc, const float* __restrict__ bc,
    float* __restrict__ out)
{
    __shared__ float sWc[640];  // [j][c] transposed
    __shared__ float sbc[10];
    const int tid = threadIdx.x;
    for (int idx = tid; idx < 640; idx += 128) {
        int j = idx / 10, c = idx % 10;
        sWc[idx] = Wc[c * 64 + j];
    }
    if (tid < 10) sbc[tid] = bc[tid];
    __syncthreads();

    const int s = blockIdx.x * 128 + tid;
    float acc[10];
#pragma unroll
    for (int c = 0; c < 10; c++) acc[c] = sbc[c];

    const float* h = g_act + (size_t)(T_STEPS - 1) * H_DIM * NSAMP + s;
#pragma unroll 4
    for (int j = 0; j < 64; j++) {
        float v = h[(size_t)j * NSAMP];
#pragma unroll
        for (int c = 0; c < 10; c++) acc[c] += v * sWc[j * 10 + c];
    }
#pragma unroll
    for (int c = 0; c < 10; c++) out[(size_t)s * 10 + c] = acc[c];
}

// ---------------------------------------------------------------------------
// Launch
// ---------------------------------------------------------------------------
extern "C" void kernel_launch(void* const* d_in, const int* in_sizes, int n_in,
                              void* d_out, int out_size)
{
    // Identify inputs by element count (robust to ordering; bih precedes bhh).
    const float *x = nullptr, *Wih0 = nullptr, *Wih = nullptr, *Whh = nullptr,
                *bih = nullptr, *bhh = nullptr, *Wc = nullptr, *bc = nullptr;
    for (int i = 0; i < n_in; i++) {
        const float* p = (const float*)d_in[i];
        switch (in_sizes[i]) {
            case NSAMP * T_STEPS * V_IN: x = p; break;       // 51380224
            case H_DIM * V_IN:           Wih0 = p; break;    // 1792
            case (L_LAYERS - 1) * H_DIM * H_DIM: Wih = p; break;  // 24576
            case L_LAYERS * H_DIM * H_DIM:       Whh = p; break;  // 28672
            case L_LAYERS * H_DIM: if (!bih) bih = p; else bhh = p; break; // 448
            case 10 * H_DIM:             Wc = p; break;      // 640
            case 10:                     bc = p; break;
        }
    }

    cudaFuncSetAttribute(rnn_layer_kernel,
                         cudaFuncAttributeMaxDynamicSharedMemorySize, SMEM_BYTES);

    // 1) transpose x into [feature][sample]
    transpose_kernel<<<dim3(NSAMP / 32, (F_TOT + 31) / 32), dim3(32, 8)>>>(x);

    // 2) seven fused RNN layers (in-place over g_act)
    for (int l = 0; l < L_LAYERS; l++) {
        const float* wih = (l == 0) ? Wih0 : (Wih + (size_t)(l - 1) * H_DIM * H_DIM);
        int in_dim = (l == 0) ? V_IN : H_DIM;
        rnn_layer_kernel<<<NSAMP / 128, 128, SMEM_BYTES>>>(
            l, in_dim, wih,
            Whh + (size_t)l * H_DIM * H_DIM,
            bih + (size_t)l * H_DIM,
            bhh + (size_t)l * H_DIM);
    }

    // 3) classifier head
    head_kernel<<<NSAMP / 128, 128>>>(Wc, bc, (float*)d_out);
}

// round 2
// speedup vs baseline: 1.0010x; 1.0010x over previous
#include <cuda_runtime.h>
#include <cuda_bf16.h>
#include <cstdint>

// ---------------------------------------------------------------------------
// Problem constants
// ---------------------------------------------------------------------------
#define NSAMP 65536
#define T_STEPS 28
#define V_IN 28
#define H_DIM 64
#define L_LAYERS 7
#define F_TOT (T_STEPS * V_IN)   // 784

// ---------------------------------------------------------------------------
// Scratch (static __device__ arrays: the sanctioned no-alloc workaround)
//   g_xT : transposed input  [t*28+i][sample]           (205 MB)
//   g_act: activations       [t*64+j][sample], in-place (470 MB)
// ---------------------------------------------------------------------------
__device__ float g_xT[(size_t)F_TOT * NSAMP];
__device__ float g_act[(size_t)T_STEPS * H_DIM * NSAMP];

// ---------------------------------------------------------------------------
// Helpers
// ---------------------------------------------------------------------------
__device__ __forceinline__ void fma2(unsigned long long& acc,
                                     unsigned long long w,
                                     unsigned long long v) {
    asm("fma.rn.f32x2 %0, %1, %2, %0;" : "+l"(acc) : "l"(w), "l"(v));
}

__device__ __forceinline__ unsigned long long pack2(float v) {
    unsigned long long r;
    asm("mov.b64 %0, {%1, %1};" : "=l"(r) : "f"(v));
    return r;
}

__device__ __forceinline__ void unpack2(unsigned long long p, float& a, float& b) {
    asm("mov.b64 {%0, %1}, %2;" : "=f"(a), "=f"(b) : "l"(p));
}

// Accurate-enough fast tanh: 1 - 2/(exp(2x)+1). ex2.approx ~2ulp -> ~1e-6 rel.
// Saturation-safe: exp->inf gives 1, exp->0 gives -1.
__device__ __forceinline__ float fast_tanh(float x) {
    float e = __expf(2.0f * x);
    return 1.0f - __fdividef(2.0f, e + 1.0f);
}

__device__ __forceinline__ void cp_async16(void* smem_dst, const void* gmem_src) {
    unsigned sm = (unsigned)__cvta_generic_to_shared(smem_dst);
    asm volatile("cp.async.cg.shared.global [%0], [%1], 16;" :: "r"(sm), "l"(gmem_src));
}
__device__ __forceinline__ void cp_commit() {
    asm volatile("cp.async.commit_group;");
}
__device__ __forceinline__ void cp_wait0() {
    asm volatile("cp.async.wait_group 0;" ::: "memory");
}

// ---------------------------------------------------------------------------
// Kernel 1: tiled transpose x (N,784) -> g_xT (784,N)
// ---------------------------------------------------------------------------
__global__ void transpose_kernel(const float* __restrict__ x) {
    __shared__ float tile[32][33];
    const int s0 = blockIdx.x * 32;
    const int f0 = blockIdx.y * 32;
    const int tx = threadIdx.x, ty = threadIdx.y;

#pragma unroll
    for (int r = 0; r < 32; r += 8) {
        int f = f0 + tx;
        float v = 0.f;
        if (f < F_TOT)
            v = x[(size_t)(s0 + ty + r) * F_TOT + f];
        tile[ty + r][tx] = v;
    }
    __syncthreads();
#pragma unroll
    for (int r = 0; r < 32; r += 8) {
        int f = f0 + ty + r;
        if (f < F_TOT)
            g_xT[(size_t)f * NSAMP + s0 + tx] = tile[tx][ty + r];
    }
}

// ---------------------------------------------------------------------------
// Kernel 2: one RNN layer, fused input-projection + recurrence.
//   One thread per sample; 128 samples per block.
//   Dynamic SMEM layout (floats):
//     sW  [0      .. 8192)   transposed weights: rows 0..IN-1 = Wih^T,
//                            rows IN..IN+63 = Whh^T  (row m: 64 floats [j])
//     sB  [8192   .. 8256)   combined bias bih+bhh
//     sIn [8256   .. 24640)  rows 0..IN-1: staged x_t slice [i][128 samples]
//                            rows IN..IN+63: hidden state   [k][128 samples]
// ---------------------------------------------------------------------------
#define SMEM_FLOATS (8192 + 64 + 16384)
#define SMEM_BYTES  (SMEM_FLOATS * 4)

__global__ __launch_bounds__(128) void rnn_layer_kernel(
    int layer, int IN,
    const float* __restrict__ Wih, const float* __restrict__ Whh,
    const float* __restrict__ bih, const float* __restrict__ bhh)
{
    extern __shared__ float smem[];
    float* sW  = smem;
    float* sB  = smem + 8192;
    float* sIn = smem + 8256;

    const int tid = threadIdx.x;
    const float* xin = (layer == 0) ? g_xT : g_act;

    // Load transposed weights: sW[m*64 + j]
    for (int idx = tid; idx < IN * 64; idx += 128) {
        int i = idx >> 6, j = idx & 63;
        sW[idx] = Wih[j * IN + i];
    }
    for (int idx = tid; idx < 64 * 64; idx += 128) {
        int k = idx >> 6, j = idx & 63;
        sW[IN * 64 + idx] = Whh[j * 64 + k];
    }
    if (tid < 64) sB[tid] = bih[tid] + bhh[tid];

    // h = 0 (each thread owns column `tid`)
#pragma unroll
    for (int k = 0; k < 64; k++) sIn[(IN + k) * 128 + tid] = 0.0f;
    __syncthreads();

    const int s0 = blockIdx.x * 128;
    const int s  = s0 + tid;
    unsigned long long p2[32];

    for (int t = 0; t < T_STEPS; t++) {
        // ---- stage x_t slice for this block's 128 samples (async) ----
        {
            const float* src = xin + (size_t)t * IN * NSAMP + s0;
            for (int v = tid; v < IN * 32; v += 128) {
                int i = v >> 5, c = v & 31;
                cp_async16(&sIn[i * 128 + 4 * c], src + (size_t)i * NSAMP + 4 * c);
            }
            cp_commit();
        }

        // ---- init accumulators with combined bias ----
#pragma unroll
        for (int jp = 0; jp < 32; jp++) {
            float2 b = *reinterpret_cast<const float2*>(&sB[2 * jp]);
            asm("mov.b64 %0, {%1, %2};" : "=l"(p2[jp]) : "f"(b.x), "f"(b.y));
        }

        // ---- recurrent half first (overlaps with cp.async of x_t) ----
        {
            const float* hcol = sIn + IN * 128 + tid;
            const float* wrow = sW + IN * 64;
#pragma unroll 2
            for (int k = 0; k < 64; k++) {
                float v = hcol[k * 128];
                unsigned long long vv = pack2(v);
                const ulonglong2* w = reinterpret_cast<const ulonglong2*>(wrow + k * 64);
#pragma unroll
                for (int q = 0; q < 16; q++) {
                    ulonglong2 ww = w[q];
                    fma2(p2[2 * q],     ww.x, vv);
                    fma2(p2[2 * q + 1], ww.y, vv);
                }
            }
        }

        cp_wait0();
        __syncthreads();

        // ---- input-projection half ----
        {
#pragma unroll 2
            for (int i = 0; i < IN; i++) {
                float v = sIn[i * 128 + tid];
                unsigned long long vv = pack2(v);
                const ulonglong2* w = reinterpret_cast<const ulonglong2*>(sW + i * 64);
#pragma unroll
                for (int q = 0; q < 16; q++) {
                    ulonglong2 ww = w[q];
                    fma2(p2[2 * q],     ww.x, vv);
                    fma2(p2[2 * q + 1], ww.y, vv);
                }
            }
        }

        // ---- tanh, write h back to SMEM (own column) and to gmem ----
        {
            float* gout = g_act + (size_t)t * H_DIM * NSAMP + s;
#pragma unroll
            for (int jp = 0; jp < 32; jp++) {
                float a, b;
                unpack2(p2[jp], a, b);
                a = fast_tanh(a);
                b = fast_tanh(b);
                sIn[(IN + 2 * jp) * 128 + tid]     = a;
                sIn[(IN + 2 * jp + 1) * 128 + tid] = b;
                gout[(size_t)(2 * jp) * NSAMP]     = a;
                gout[(size_t)(2 * jp + 1) * NSAMP] = b;
            }
        }
        __syncthreads();  // protect x rows before next step's cp.async
    }
}

// ---------------------------------------------------------------------------
// Kernel 3: classifier head  out[s][c] = bc[c] + sum_j Wc[c][j] * h_last[j][s]
// ---------------------------------------------------------------------------
__global__ __launch_bounds__(128) void head_kernel(
    const float* __restrict__ Wc, const float* __restrict__ bc,
    float* __restrict__ out)
{
    __shared__ float sWc[640];  // [j][c] transposed
    __shared__ float sbc[10];
    const int tid = threadIdx.x;
    for (int idx = tid; idx < 640; idx += 128) {
        int j = idx / 10, c = idx % 10;
        sWc[idx] = Wc[c * 64 + j];
    }
    if (tid < 10) sbc[tid] = bc[tid];
    __syncthreads();

    const int s = blockIdx.x * 128 + tid;
    float acc[10];
#pragma unroll
    for (int c = 0; c < 10; c++) acc[c] = sbc[c];

    const float* h = g_act + (size_t)(T_STEPS - 1) * H_DIM * NSAMP + s;
#pragma unroll 4
    for (int j = 0; j < 64; j++) {
        float v = h[(size_t)j * NSAMP];
#pragma unroll
        for (int c = 0; c < 10; c++) acc[c] += v * sWc[j * 10 + c];
    }
#pragma unroll
    for (int c = 0; c < 10; c++) out[(size_t)s * 10 + c] = acc[c];
}

// ---------------------------------------------------------------------------
// Launch
// ---------------------------------------------------------------------------
extern "C" void kernel_launch(void* const* d_in, const int* in_sizes, int n_in,
                              void* d_out, int out_size)
{
    // Identify inputs by element count (robust to ordering; bih precedes bhh).
    const float *x = nullptr, *Wih0 = nullptr, *Wih = nullptr, *Whh = nullptr,
                *bih = nullptr, *bhh = nullptr, *Wc = nullptr, *bc = nullptr;
    for (int i = 0; i < n_in; i++) {
        const float* p = (const float*)d_in[i];
        switch (in_sizes[i]) {
            case NSAMP * T_STEPS * V_IN: x = p; break;       // 51380224
            case H_DIM * V_IN:           Wih0 = p; break;    // 1792
            case (L_LAYERS - 1) * H_DIM * H_DIM: Wih = p; break;  // 24576
            case L_LAYERS * H_DIM * H_DIM:       Whh = p; break;  // 28672
            case L_LAYERS * H_DIM: if (!bih) bih = p; else bhh = p; break; // 448
            case 10 * H_DIM:             Wc = p; break;      // 640
            case 10:                     bc = p; break;
        }
    }

    cudaFuncSetAttribute(rnn_layer_kernel,
                         cudaFuncAttributeMaxDynamicSharedMemorySize, SMEM_BYTES);

    // 1) transpose x into [feature][sample]
    transpose_kernel<<<dim3(NSAMP / 32, (F_TOT + 31) / 32), dim3(32, 8)>>>(x);

    // 2) seven fused RNN layers (in-place over g_act)
    for (int l = 0; l < L_LAYERS; l++) {
        const float* wih = (l == 0) ? Wih0 : (Wih + (size_t)(l - 1) * H_DIM * H_DIM);
        int in_dim = (l == 0) ? V_IN : H_DIM;
        rnn_layer_kernel<<<NSAMP / 128, 128, SMEM_BYTES>>>(
            l, in_dim, wih,
            Whh + (size_t)l * H_DIM * H_DIM,
            bih + (size_t)l * H_DIM,
            bhh + (size_t)l * H_DIM);
    }

    // 3) classifier head
    head_kernel<<<NSAMP / 128, 128>>>(Wc, bc, (float*)d_out);
}